// round 13
// baseline (speedup 1.0000x reference)
#include <cuda_runtime.h>
#include <math.h>

#define N_NODES 100000
#define F_IN    256
#define HID     128
#define CH      16
#define NE      3200000
#define K_HOPS  10
#define NBLK    ((N_NODES + 255) / 256)   // 391
#define LDA     33                        // uint2 per smem row (32 + 1 pad)

// Scratch (allocation-free rule: __device__ globals)
__device__ float g_h1[(size_t)N_NODES * HID];                    // 51.2 MB
__device__ float g_pps[(size_t)(K_HOPS + 1) * N_NODES * CH];     // 70.4 MB
__device__ int2  g_csr[NE];                                      // 25.6 MB (src, attr-bits), dst-sorted
__device__ int   g_cnt[N_NODES];
__device__ int   g_row[N_NODES + 1];
__device__ int   g_cursor[N_NODES];
__device__ int   g_bsum[NBLK];
__device__ int   g_boff[NBLK];
__device__ int   g_is64;

// tf32 helpers
__device__ __forceinline__ unsigned int f2tf32(float f)
{
    unsigned int u;
    asm("cvt.rna.tf32.f32 %0, %1;" : "=r"(u) : "f"(f));
    return u;
}

// pack one fp32 value into (hi, lo) tf32 pair
__device__ __forceinline__ uint2 tf32_split(float f)
{
    unsigned int hi = f2tf32(f);
    unsigned int lo = f2tf32(f - __uint_as_float(hi));
    return make_uint2(hi, lo);
}

#define MMA_TF32(d0, d1, d2, d3, a0, a1, a2, a3, b0, b1)                    \
    asm("mma.sync.aligned.m16n8k8.row.col.f32.tf32.tf32.f32 "               \
        "{%0,%1,%2,%3}, {%4,%5,%6,%7}, {%8,%9}, {%0,%1,%2,%3};"             \
        : "+f"(d0), "+f"(d1), "+f"(d2), "+f"(d3)                            \
        : "r"(a0), "r"(a1), "r"(a2), "r"(a3), "r"(b0), "r"(b1))

// ---------------------------------------------------------------------------
// edge_index dtype detection (int64 vs int32) — warp-parallel, ballot.
// ---------------------------------------------------------------------------
__global__ void detect_idx_dtype(const unsigned int* __restrict__ w)
{
    const int lane = threadIdx.x & 31;
    unsigned int bad = 0u;
#pragma unroll 8
    for (int i = lane * 2 + 1; i < 8192; i += 64)
        bad |= w[i];
    unsigned int any = __ballot_sync(0xffffffffu, bad != 0u);
    if (lane == 0) g_is64 = (any == 0u) ? 1 : 0;
}

// ---------------------------------------------------------------------------
// CSR build: histogram -> block scans -> scatter
// ---------------------------------------------------------------------------
__global__ void zero_cnt()
{
    int i = blockIdx.x * blockDim.x + threadIdx.x;
    if (i < N_NODES) g_cnt[i] = 0;
}

__global__ void hist_kernel(const void* __restrict__ ei_raw)
{
    int e = blockIdx.x * blockDim.x + threadIdx.x;
    if (e >= NE) return;
    int d = g_is64 ? (int)((const long long*)ei_raw)[(size_t)NE + e]
                   : ((const int*)ei_raw)[(size_t)NE + e];
    if ((unsigned)d < N_NODES) atomicAdd(&g_cnt[d], 1);
}

__global__ void scan_blocks()
{
    __shared__ int s[256];
    int tid = threadIdx.x;
    int idx = blockIdx.x * 256 + tid;
    int v = (idx < N_NODES) ? g_cnt[idx] : 0;
    s[tid] = v;
    __syncthreads();
#pragma unroll
    for (int off = 1; off < 256; off <<= 1) {
        int t = (tid >= off) ? s[tid - off] : 0;
        __syncthreads();
        s[tid] += t;
        __syncthreads();
    }
    if (idx < N_NODES) g_row[idx] = s[tid] - v;     // local exclusive
    if (tid == 255) g_bsum[blockIdx.x] = s[255];
}

__global__ void scan_tops()
{
    __shared__ int s[512];
    int tid = threadIdx.x;
    int v = (tid < NBLK) ? g_bsum[tid] : 0;
    s[tid] = v;
    __syncthreads();
#pragma unroll
    for (int off = 1; off < 512; off <<= 1) {
        int t = (tid >= off) ? s[tid - off] : 0;
        __syncthreads();
        s[tid] += t;
        __syncthreads();
    }
    if (tid < NBLK) g_boff[tid] = s[tid] - v;       // exclusive over block sums
}

__global__ void finalize_row()
{
    int idx = blockIdx.x * 256 + threadIdx.x;
    if (idx < N_NODES) {
        int r = g_row[idx] + g_boff[blockIdx.x];
        g_row[idx] = r;
        g_cursor[idx] = r;
    }
    if (idx == 0) g_row[N_NODES] = NE;
}

__global__ void scatter_csr(const void* __restrict__ ei_raw,
                            const float* __restrict__ attr)
{
    int e = blockIdx.x * blockDim.x + threadIdx.x;
    if (e >= NE) return;
    int s, d;
    if (g_is64) {
        const long long* ei = (const long long*)ei_raw;
        s = (int)ei[e];
        d = (int)ei[(size_t)NE + e];
    } else {
        const int* ei = (const int*)ei_raw;
        s = ei[e];
        d = ei[(size_t)NE + e];
    }
    if ((unsigned)s >= N_NODES || (unsigned)d >= N_NODES) return;
    int slot = atomicAdd(&g_cursor[d], 1);
    g_csr[slot] = make_int2(s, __float_as_int(attr[e]));
}

// ---------------------------------------------------------------------------
// Layer 1 GEMM, tensor pipe, 3xTF32 with hi/lo PRE-CONVERTED in smem.
// g_h1 = relu(x @ W1^T + b1).  BM=128, BK=32, 8 warps (2m x 4n), warp 64x32.
// Inner loop is pure LDS.64 + MMA (no cvt).
// ---------------------------------------------------------------------------
__global__ __launch_bounds__(256, 2)
void gemm1_tf32(const float* __restrict__ X,
                const float* __restrict__ W,
                const float* __restrict__ bias)
{
    constexpr int BM = 128, BK = 32, Kd = F_IN, Nd = HID;
    const int M = N_NODES;

    extern __shared__ char smem_raw[];
    uint2 (*As2)[LDA] = (uint2(*)[LDA])smem_raw;                 // 128 x 33 uint2
    uint2 (*Ws2)[LDA] = (uint2(*)[LDA])(smem_raw + BM * LDA * 8);

    const int tid  = threadIdx.x;
    const int lane = tid & 31;
    const int wid  = tid >> 5;            // 0..7
    const int wm   = (wid >> 2) * 64;     // 0 or 64
    const int wn   = (wid & 3) * 32;      // 0,32,64,96
    const int lr   = lane >> 2;           // 0..7
    const int lc   = lane & 3;            // 0..3
    const int bm   = blockIdx.x * BM;

    float acc[4][4][4];
#pragma unroll
    for (int i = 0; i < 4; i++)
#pragma unroll
        for (int j = 0; j < 4; j++)
#pragma unroll
            for (int r = 0; r < 4; r++) acc[i][j][r] = 0.f;

    const int grow = tid >> 3;            // 0..31
    const int gcol = (tid & 7) * 4;       // 0,4,...,28

    for (int s = 0; s < Kd / BK; s++) {
        const int k0 = s * BK;
#pragma unroll
        for (int r = 0; r < 4; r++) {
            int row = grow + r * 32;
            int gm  = bm + row;
            float4 v = make_float4(0.f, 0.f, 0.f, 0.f);
            if (gm < M)
                v = *reinterpret_cast<const float4*>(&X[(size_t)gm * Kd + k0 + gcol]);
            As2[row][gcol + 0] = tf32_split(v.x);
            As2[row][gcol + 1] = tf32_split(v.y);
            As2[row][gcol + 2] = tf32_split(v.z);
            As2[row][gcol + 3] = tf32_split(v.w);
            float4 wv = *reinterpret_cast<const float4*>(&W[(size_t)row * Kd + k0 + gcol]);
            Ws2[row][gcol + 0] = tf32_split(wv.x);
            Ws2[row][gcol + 1] = tf32_split(wv.y);
            Ws2[row][gcol + 2] = tf32_split(wv.z);
            Ws2[row][gcol + 3] = tf32_split(wv.w);
        }
        __syncthreads();

#pragma unroll
        for (int k = 0; k < BK; k += 8) {
            uint2 b0[4], b1[4];
#pragma unroll
            for (int fn = 0; fn < 4; fn++) {
                int n0 = wn + fn * 8;
                b0[fn] = Ws2[n0 + lr][k + lc];
                b1[fn] = Ws2[n0 + lr][k + lc + 4];
            }
#pragma unroll
            for (int fm = 0; fm < 4; fm++) {
                int m0 = wm + fm * 16;
                uint2 a0 = As2[m0 + lr][k + lc];
                uint2 a1 = As2[m0 + lr + 8][k + lc];
                uint2 a2 = As2[m0 + lr][k + lc + 4];
                uint2 a3 = As2[m0 + lr + 8][k + lc + 4];
#pragma unroll
                for (int fn = 0; fn < 4; fn++) {
                    MMA_TF32(acc[fm][fn][0], acc[fm][fn][1], acc[fm][fn][2], acc[fm][fn][3],
                             a0.x, a1.x, a2.x, a3.x, b0[fn].x, b1[fn].x);   // hh
                    MMA_TF32(acc[fm][fn][0], acc[fm][fn][1], acc[fm][fn][2], acc[fm][fn][3],
                             a0.x, a1.x, a2.x, a3.x, b0[fn].y, b1[fn].y);   // h*l
                    MMA_TF32(acc[fm][fn][0], acc[fm][fn][1], acc[fm][fn][2], acc[fm][fn][3],
                             a0.y, a1.y, a2.y, a3.y, b0[fn].x, b1[fn].x);   // l*h
                }
            }
        }
        __syncthreads();
    }

#pragma unroll
    for (int fm = 0; fm < 4; fm++) {
#pragma unroll
        for (int fn = 0; fn < 4; fn++) {
            int c0 = wn + fn * 8 + lc * 2;
            float bx = bias[c0], by = bias[c0 + 1];
            int r0 = bm + wm + fm * 16 + lr;
            int r1 = r0 + 8;
            if (r0 < M) {
                float2 o;
                o.x = fmaxf(acc[fm][fn][0] + bx, 0.f);
                o.y = fmaxf(acc[fm][fn][1] + by, 0.f);
                *reinterpret_cast<float2*>(&g_h1[(size_t)r0 * Nd + c0]) = o;
            }
            if (r1 < M) {
                float2 o;
                o.x = fmaxf(acc[fm][fn][2] + bx, 0.f);
                o.y = fmaxf(acc[fm][fn][3] + by, 0.f);
                *reinterpret_cast<float2*>(&g_h1[(size_t)r1 * Nd + c0]) = o;
            }
        }
    }
}

// ---------------------------------------------------------------------------
// Fused layer2+layer3, tf32 tensor mainloop (same pattern), then
// h2 tile -> smem, pps[0] = relu(h2 @ W3^T + b3).
// smem: [0, 67584)  tf32 stage tiles  /  h2s after mainloop (aliased)
//       [67584, +8192)  W3s transposed, then b3s.
// ---------------------------------------------------------------------------
#define H2_LD (HID + 4)
#define STAGE_BYTES (128 * LDA * 8 * 2)          // 67584: As2 + Ws2
__global__ __launch_bounds__(256, 2)
void gemm2_lin3_fused(const float* __restrict__ b2,
                      const float* __restrict__ W2,
                      const float* __restrict__ W3,
                      const float* __restrict__ b3)
{
    constexpr int BM = 128, BK = 32, Kd = HID;
    const int M = N_NODES;
    const float* __restrict__ A = g_h1;

    extern __shared__ char smem_raw[];
    uint2 (*As2)[LDA]   = (uint2(*)[LDA])smem_raw;
    uint2 (*Ws2)[LDA]   = (uint2(*)[LDA])(smem_raw + BM * LDA * 8);
    float (*h2s)[H2_LD] = (float(*)[H2_LD])smem_raw;
    float (*W3s)[CH]    = (float(*)[CH])(smem_raw + STAGE_BYTES);
    float* b3s          = (float*)(smem_raw + STAGE_BYTES + HID * CH * 4);

    const int tid  = threadIdx.x;
    const int lane = tid & 31;
    const int wid  = tid >> 5;
    const int wm   = (wid >> 2) * 64;
    const int wn   = (wid & 3) * 32;
    const int lr   = lane >> 2;
    const int lc   = lane & 3;
    const int bm   = blockIdx.x * BM;

    for (int i = tid; i < CH * HID; i += 256) {
        int c = i / HID, k = i % HID;
        W3s[k][c] = W3[(size_t)c * HID + k];
    }
    if (tid < CH) b3s[tid] = b3[tid];

    float acc[4][4][4];
#pragma unroll
    for (int i = 0; i < 4; i++)
#pragma unroll
        for (int j = 0; j < 4; j++)
#pragma unroll
            for (int r = 0; r < 4; r++) acc[i][j][r] = 0.f;

    const int grow = tid >> 3;
    const int gcol = (tid & 7) * 4;

    for (int s = 0; s < Kd / BK; s++) {
        const int k0 = s * BK;
#pragma unroll
        for (int r = 0; r < 4; r++) {
            int row = grow + r * 32;
            int gm  = bm + row;
            float4 v = make_float4(0.f, 0.f, 0.f, 0.f);
            if (gm < M)
                v = *reinterpret_cast<const float4*>(&A[(size_t)gm * Kd + k0 + gcol]);
            As2[row][gcol + 0] = tf32_split(v.x);
            As2[row][gcol + 1] = tf32_split(v.y);
            As2[row][gcol + 2] = tf32_split(v.z);
            As2[row][gcol + 3] = tf32_split(v.w);
            float4 wv = *reinterpret_cast<const float4*>(&W2[(size_t)row * Kd + k0 + gcol]);
            Ws2[row][gcol + 0] = tf32_split(wv.x);
            Ws2[row][gcol + 1] = tf32_split(wv.y);
            Ws2[row][gcol + 2] = tf32_split(wv.z);
            Ws2[row][gcol + 3] = tf32_split(wv.w);
        }
        __syncthreads();

#pragma unroll
        for (int k = 0; k < BK; k += 8) {
            uint2 b0[4], b1[4];
#pragma unroll
            for (int fn = 0; fn < 4; fn++) {
                int n0 = wn + fn * 8;
                b0[fn] = Ws2[n0 + lr][k + lc];
                b1[fn] = Ws2[n0 + lr][k + lc + 4];
            }
#pragma unroll
            for (int fm = 0; fm < 4; fm++) {
                int m0 = wm + fm * 16;
                uint2 a0 = As2[m0 + lr][k + lc];
                uint2 a1 = As2[m0 + lr + 8][k + lc];
                uint2 a2 = As2[m0 + lr][k + lc + 4];
                uint2 a3 = As2[m0 + lr + 8][k + lc + 4];
#pragma unroll
                for (int fn = 0; fn < 4; fn++) {
                    MMA_TF32(acc[fm][fn][0], acc[fm][fn][1], acc[fm][fn][2], acc[fm][fn][3],
                             a0.x, a1.x, a2.x, a3.x, b0[fn].x, b1[fn].x);
                    MMA_TF32(acc[fm][fn][0], acc[fm][fn][1], acc[fm][fn][2], acc[fm][fn][3],
                             a0.x, a1.x, a2.x, a3.x, b0[fn].y, b1[fn].y);
                    MMA_TF32(acc[fm][fn][0], acc[fm][fn][1], acc[fm][fn][2], acc[fm][fn][3],
                             a0.y, a1.y, a2.y, a3.y, b0[fn].x, b1[fn].x);
                }
            }
        }
        __syncthreads();   // after final stage, As2/Ws2 dead -> h2s aliases them
    }

    // bias2 + relu -> h2 tile in smem (scalar stores from MMA fragments)
#pragma unroll
    for (int fm = 0; fm < 4; fm++) {
#pragma unroll
        for (int fn = 0; fn < 4; fn++) {
            int c0 = wn + fn * 8 + lc * 2;
            float bx = b2[c0], by = b2[c0 + 1];
            int r0 = wm + fm * 16 + lr;
            int r1 = r0 + 8;
            h2s[r0][c0]     = fmaxf(acc[fm][fn][0] + bx, 0.f);
            h2s[r0][c0 + 1] = fmaxf(acc[fm][fn][1] + by, 0.f);
            h2s[r1][c0]     = fmaxf(acc[fm][fn][2] + bx, 0.f);
            h2s[r1][c0 + 1] = fmaxf(acc[fm][fn][3] + by, 0.f);
        }
    }
    __syncthreads();

    // pps[0] = relu(h2 @ W3^T + b3)
    const int c2 = tid & 15;
    const int g2 = tid >> 4;
    const float b3v = b3s[c2];
#pragma unroll
    for (int i = 0; i < 8; i++) {
        int r = g2 * 8 + i;
        float acc3 = 0.f;
#pragma unroll
        for (int k = 0; k < HID; k += 4) {
            float4 hv = *reinterpret_cast<const float4*>(&h2s[r][k]);
            acc3 += hv.x * W3s[k + 0][c2];
            acc3 += hv.y * W3s[k + 1][c2];
            acc3 += hv.z * W3s[k + 2][c2];
            acc3 += hv.w * W3s[k + 3][c2];
        }
        int gm = bm + r;
        if (gm < M)
            g_pps[(size_t)gm * CH + c2] = fmaxf(acc3 + b3v, 0.f);
    }
}

// ---------------------------------------------------------------------------
// Pull-mode hop: warp per dst node, 4 lanes/edge x 8 edges/iter,
// 2-way unrolled, shfl-reduce, coalesced float4 store. No atomics.
// ---------------------------------------------------------------------------
__global__ void hop_pull(int k)
{
    const float* __restrict__ hin = g_pps + (size_t)k * N_NODES * CH;
    float* __restrict__ hout = g_pps + (size_t)(k + 1) * N_NODES * CH;

    int node = (blockIdx.x * blockDim.x + threadIdx.x) >> 5;
    if (node >= N_NODES) return;
    const int lane = threadIdx.x & 31;
    const int w = lane >> 2;
    const int q = lane & 3;
    const int qoff = q * 4;

    const int rs = __ldg(&g_row[node]);
    const int re = __ldg(&g_row[node + 1]);

    float4 acc0 = make_float4(0.f, 0.f, 0.f, 0.f);
    float4 acc1 = make_float4(0.f, 0.f, 0.f, 0.f);

    int e = rs + w;
    for (; e + 8 < re; e += 16) {
        int2 ed0 = __ldg(&g_csr[e]);
        int2 ed1 = __ldg(&g_csr[e + 8]);
        float4 v0 = *reinterpret_cast<const float4*>(hin + ed0.x * CH + qoff);
        float4 v1 = *reinterpret_cast<const float4*>(hin + ed1.x * CH + qoff);
        float w0 = __int_as_float(ed0.y);
        float w1 = __int_as_float(ed1.y);
        acc0.x += w0 * v0.x; acc0.y += w0 * v0.y;
        acc0.z += w0 * v0.z; acc0.w += w0 * v0.w;
        acc1.x += w1 * v1.x; acc1.y += w1 * v1.y;
        acc1.z += w1 * v1.z; acc1.w += w1 * v1.w;
    }
    if (e < re) {
        int2 ed0 = __ldg(&g_csr[e]);
        float4 v0 = *reinterpret_cast<const float4*>(hin + ed0.x * CH + qoff);
        float w0 = __int_as_float(ed0.y);
        acc0.x += w0 * v0.x; acc0.y += w0 * v0.y;
        acc0.z += w0 * v0.z; acc0.w += w0 * v0.w;
    }

    float4 acc = make_float4(acc0.x + acc1.x, acc0.y + acc1.y,
                             acc0.z + acc1.z, acc0.w + acc1.w);

#pragma unroll
    for (int off = 4; off <= 16; off <<= 1) {
        acc.x += __shfl_xor_sync(0xffffffff, acc.x, off);
        acc.y += __shfl_xor_sync(0xffffffff, acc.y, off);
        acc.z += __shfl_xor_sync(0xffffffff, acc.z, off);
        acc.w += __shfl_xor_sync(0xffffffff, acc.w, off);
    }

    if (w == 0)
        *reinterpret_cast<float4*>(hout + node * CH + qoff) = acc;
}

// ---------------------------------------------------------------------------
// Combine
// ---------------------------------------------------------------------------
__global__ void combine_kernel(const float* __restrict__ proj_w,
                               const float* __restrict__ proj_b,
                               float* __restrict__ out)
{
    int n = blockIdx.x * blockDim.x + threadIdx.x;
    if (n >= N_NODES) return;

    float w[CH];
#pragma unroll
    for (int c = 0; c < CH; c++) w[c] = proj_w[c];
    const float pb = proj_b[0];

    float acc[CH];
#pragma unroll
    for (int c = 0; c < CH; c++) acc[c] = 0.f;

#pragma unroll
    for (int k = 0; k <= K_HOPS; k++) {
        const float4* p = reinterpret_cast<const float4*>(
            g_pps + (size_t)k * N_NODES * CH + (size_t)n * CH);
        float4 v0 = p[0], v1 = p[1], v2 = p[2], v3 = p[3];
        float pv[CH] = {v0.x, v0.y, v0.z, v0.w, v1.x, v1.y, v1.z, v1.w,
                        v2.x, v2.y, v2.z, v2.w, v3.x, v3.y, v3.z, v3.w};
        float sdot = pb;
#pragma unroll
        for (int c = 0; c < CH; c++) sdot += pv[c] * w[c];
        float s = 1.0f / (1.0f + expf(-sdot));
#pragma unroll
        for (int c = 0; c < CH; c++) acc[c] += s * pv[c];
    }

    float4* o = reinterpret_cast<float4*>(out + (size_t)n * CH);
    o[0] = make_float4(acc[0],  acc[1],  acc[2],  acc[3]);
    o[1] = make_float4(acc[4],  acc[5],  acc[6],  acc[7]);
    o[2] = make_float4(acc[8],  acc[9],  acc[10], acc[11]);
    o[3] = make_float4(acc[12], acc[13], acc[14], acc[15]);
}

// ---------------------------------------------------------------------------
extern "C" void kernel_launch(void* const* d_in, const int* in_sizes, int n_in,
                              void* d_out, int out_size)
{
    const float* x    = (const float*)d_in[0];
    const void*  ei   = d_in[1];
    const float* attr = (const float*)d_in[2];
    const float* w1   = (const float*)d_in[3];
    const float* b1   = (const float*)d_in[4];
    const float* w2   = (const float*)d_in[5];
    const float* b2   = (const float*)d_in[6];
    const float* w3   = (const float*)d_in[7];
    const float* b3   = (const float*)d_in[8];
    const float* pw   = (const float*)d_in[9];
    const float* pbv  = (const float*)d_in[10];
    float* out = (float*)d_out;

    const int G1_SMEM = STAGE_BYTES;                             // 67584
    const int G2_SMEM = STAGE_BYTES + HID * CH * 4 + 64;         // ~75.9 KB
    cudaFuncSetAttribute(gemm1_tf32,
                         cudaFuncAttributeMaxDynamicSharedMemorySize, G1_SMEM);
    cudaFuncSetAttribute(gemm2_lin3_fused,
                         cudaFuncAttributeMaxDynamicSharedMemorySize, G2_SMEM);

    const int EB = (NE + 255) / 256;
    const int grid1 = (N_NODES + 127) / 128;

    // Launch order keeps gemm1_tf32 at slot 4 — the slot ncu captures.
    detect_idx_dtype<<<1, 32>>>((const unsigned int*)ei);           // 1
    zero_cnt<<<NBLK, 256>>>();                                      // 2
    hist_kernel<<<EB, 256>>>(ei);                                   // 3
    gemm1_tf32<<<grid1, 256, G1_SMEM>>>(x, w1, b1);                 // 4  <- profiled
    scan_blocks<<<NBLK, 256>>>();                                   // 5
    scan_tops<<<1, 512>>>();                                        // 6
    finalize_row<<<NBLK, 256>>>();                                  // 7
    scatter_csr<<<EB, 256>>>(ei, attr);                             // 8
    gemm2_lin3_fused<<<grid1, 256, G2_SMEM>>>(b2, w2, w3, b3);      // 9

    // K pull-mode hops (warp per node)
    {
        int blocks = (N_NODES * 32 + 255) / 256;
        for (int k = 0; k < K_HOPS; k++)
            hop_pull<<<blocks, 256>>>(k);
    }

    combine_kernel<<<(N_NODES + 255) / 256, 256>>>(pw, pbv, out);
}

// round 14
// speedup vs baseline: 1.1721x; 1.1721x over previous
#include <cuda_runtime.h>
#include <math.h>

#define N_NODES 100000
#define F_IN    256
#define HID     128
#define CH      16
#define NE      3200000
#define K_HOPS  10
#define NBLK    ((N_NODES + 255) / 256)   // 391

#define SLD     36                        // smem row stride (floats): bank = 4*lr+lc = lane, conflict-free
#define SARR    (128 * SLD)               // floats per stage array
#define STAGE_BYTES (4 * SARR * 4)        // 73728 B: Ah, Al, Wh, Wl

// Scratch (allocation-free rule: __device__ globals)
__device__ float g_h1[(size_t)N_NODES * HID];                    // 51.2 MB
__device__ float g_pps[(size_t)(K_HOPS + 1) * N_NODES * CH];     // 70.4 MB
__device__ int2  g_csr[NE];                                      // 25.6 MB (src, attr-bits), dst-sorted
__device__ int   g_cnt[N_NODES];
__device__ int   g_row[N_NODES + 1];
__device__ int   g_cursor[N_NODES];
__device__ int   g_bsum[NBLK];
__device__ int   g_boff[NBLK];
__device__ int   g_is64;

// tf32 helpers
__device__ __forceinline__ unsigned int f2tf32(float f)
{
    unsigned int u;
    asm("cvt.rna.tf32.f32 %0, %1;" : "=r"(u) : "f"(f));
    return u;
}

#define MMA_TF32(d0, d1, d2, d3, a0, a1, a2, a3, b0, b1)                    \
    asm("mma.sync.aligned.m16n8k8.row.col.f32.tf32.tf32.f32 "               \
        "{%0,%1,%2,%3}, {%4,%5,%6,%7}, {%8,%9}, {%0,%1,%2,%3};"             \
        : "+f"(d0), "+f"(d1), "+f"(d2), "+f"(d3)                            \
        : "r"(a0), "r"(a1), "r"(a2), "r"(a3), "r"(b0), "r"(b1))

// split f into tf32 (hi, lo) and store to the two arrays
__device__ __forceinline__ void split_store(float* hi_arr, float* lo_arr,
                                            int idx, float f)
{
    unsigned int hi = f2tf32(f);
    unsigned int lo = f2tf32(f - __uint_as_float(hi));
    hi_arr[idx] = __uint_as_float(hi);
    lo_arr[idx] = __uint_as_float(lo);
}

// ---------------------------------------------------------------------------
// edge_index dtype detection (int64 vs int32) — warp-parallel, ballot.
// ---------------------------------------------------------------------------
__global__ void detect_idx_dtype(const unsigned int* __restrict__ w)
{
    const int lane = threadIdx.x & 31;
    unsigned int bad = 0u;
#pragma unroll 8
    for (int i = lane * 2 + 1; i < 8192; i += 64)
        bad |= w[i];
    unsigned int any = __ballot_sync(0xffffffffu, bad != 0u);
    if (lane == 0) g_is64 = (any == 0u) ? 1 : 0;
}

// ---------------------------------------------------------------------------
// CSR build: histogram -> block scans -> scatter
// ---------------------------------------------------------------------------
__global__ void zero_cnt()
{
    int i = blockIdx.x * blockDim.x + threadIdx.x;
    if (i < N_NODES) g_cnt[i] = 0;
}

__global__ void hist_kernel(const void* __restrict__ ei_raw)
{
    int e = blockIdx.x * blockDim.x + threadIdx.x;
    if (e >= NE) return;
    int d = g_is64 ? (int)((const long long*)ei_raw)[(size_t)NE + e]
                   : ((const int*)ei_raw)[(size_t)NE + e];
    if ((unsigned)d < N_NODES) atomicAdd(&g_cnt[d], 1);
}

__global__ void scan_blocks()
{
    __shared__ int s[256];
    int tid = threadIdx.x;
    int idx = blockIdx.x * 256 + tid;
    int v = (idx < N_NODES) ? g_cnt[idx] : 0;
    s[tid] = v;
    __syncthreads();
#pragma unroll
    for (int off = 1; off < 256; off <<= 1) {
        int t = (tid >= off) ? s[tid - off] : 0;
        __syncthreads();
        s[tid] += t;
        __syncthreads();
    }
    if (idx < N_NODES) g_row[idx] = s[tid] - v;     // local exclusive
    if (tid == 255) g_bsum[blockIdx.x] = s[255];
}

__global__ void scan_tops()
{
    __shared__ int s[512];
    int tid = threadIdx.x;
    int v = (tid < NBLK) ? g_bsum[tid] : 0;
    s[tid] = v;
    __syncthreads();
#pragma unroll
    for (int off = 1; off < 512; off <<= 1) {
        int t = (tid >= off) ? s[tid - off] : 0;
        __syncthreads();
        s[tid] += t;
        __syncthreads();
    }
    if (tid < NBLK) g_boff[tid] = s[tid] - v;       // exclusive over block sums
}

__global__ void finalize_row()
{
    int idx = blockIdx.x * 256 + threadIdx.x;
    if (idx < N_NODES) {
        int r = g_row[idx] + g_boff[blockIdx.x];
        g_row[idx] = r;
        g_cursor[idx] = r;
    }
    if (idx == 0) g_row[N_NODES] = NE;
}

__global__ void scatter_csr(const void* __restrict__ ei_raw,
                            const float* __restrict__ attr)
{
    int e = blockIdx.x * blockDim.x + threadIdx.x;
    if (e >= NE) return;
    int s, d;
    if (g_is64) {
        const long long* ei = (const long long*)ei_raw;
        s = (int)ei[e];
        d = (int)ei[(size_t)NE + e];
    } else {
        const int* ei = (const int*)ei_raw;
        s = ei[e];
        d = ei[(size_t)NE + e];
    }
    if ((unsigned)s >= N_NODES || (unsigned)d >= N_NODES) return;
    int slot = atomicAdd(&g_cursor[d], 1);
    g_csr[slot] = make_int2(s, __float_as_int(attr[e]));
}

// ---------------------------------------------------------------------------
// Layer 1 GEMM, tensor pipe, 3xTF32. hi/lo pre-converted into FOUR separate
// float arrays, row stride 36 floats => every fragment LDS.32 is
// bank-conflict-free (bank = 4*lr + lc = lane).
// g_h1 = relu(x @ W1^T + b1).  BM=128, BK=32, 8 warps (2m x 4n).
// ---------------------------------------------------------------------------
__global__ __launch_bounds__(256, 2)
void gemm1_tf32(const float* __restrict__ X,
                const float* __restrict__ W,
                const float* __restrict__ bias)
{
    constexpr int BM = 128, BK = 32, Kd = F_IN, Nd = HID;
    const int M = N_NODES;

    extern __shared__ float sm[];
    float* Ah = sm;
    float* Al = sm + SARR;
    float* Wh = sm + 2 * SARR;
    float* Wl = sm + 3 * SARR;

    const int tid  = threadIdx.x;
    const int lane = tid & 31;
    const int wid  = tid >> 5;            // 0..7
    const int wm   = (wid >> 2) * 64;     // 0 or 64
    const int wn   = (wid & 3) * 32;      // 0,32,64,96
    const int lr   = lane >> 2;           // 0..7
    const int lc   = lane & 3;            // 0..3
    const int bm   = blockIdx.x * BM;

    float acc[4][4][4];
#pragma unroll
    for (int i = 0; i < 4; i++)
#pragma unroll
        for (int j = 0; j < 4; j++)
#pragma unroll
            for (int r = 0; r < 4; r++) acc[i][j][r] = 0.f;

    const int grow = tid >> 3;            // 0..31
    const int gcol = (tid & 7) * 4;       // 0,4,...,28

    for (int s = 0; s < Kd / BK; s++) {
        const int k0 = s * BK;
#pragma unroll
        for (int r = 0; r < 4; r++) {
            int row = grow + r * 32;
            int gm  = bm + row;
            float4 v = make_float4(0.f, 0.f, 0.f, 0.f);
            if (gm < M)
                v = *reinterpret_cast<const float4*>(&X[(size_t)gm * Kd + k0 + gcol]);
            int base = row * SLD + gcol;
            split_store(Ah, Al, base + 0, v.x);
            split_store(Ah, Al, base + 1, v.y);
            split_store(Ah, Al, base + 2, v.z);
            split_store(Ah, Al, base + 3, v.w);
            float4 wv = *reinterpret_cast<const float4*>(&W[(size_t)row * Kd + k0 + gcol]);
            split_store(Wh, Wl, base + 0, wv.x);
            split_store(Wh, Wl, base + 1, wv.y);
            split_store(Wh, Wl, base + 2, wv.z);
            split_store(Wh, Wl, base + 3, wv.w);
        }
        __syncthreads();

#pragma unroll
        for (int k = 0; k < BK; k += 8) {
            unsigned int bh0[4], bh1[4], bl0[4], bl1[4];
#pragma unroll
            for (int fn = 0; fn < 4; fn++) {
                int base = (wn + fn * 8 + lr) * SLD + k + lc;
                bh0[fn] = __float_as_uint(Wh[base]);
                bh1[fn] = __float_as_uint(Wh[base + 4]);
                bl0[fn] = __float_as_uint(Wl[base]);
                bl1[fn] = __float_as_uint(Wl[base + 4]);
            }
#pragma unroll
            for (int fm = 0; fm < 4; fm++) {
                int base = (wm + fm * 16 + lr) * SLD + k + lc;
                unsigned int ah0 = __float_as_uint(Ah[base]);
                unsigned int ah1 = __float_as_uint(Ah[base + 8 * SLD]);
                unsigned int ah2 = __float_as_uint(Ah[base + 4]);
                unsigned int ah3 = __float_as_uint(Ah[base + 8 * SLD + 4]);
                unsigned int al0 = __float_as_uint(Al[base]);
                unsigned int al1 = __float_as_uint(Al[base + 8 * SLD]);
                unsigned int al2 = __float_as_uint(Al[base + 4]);
                unsigned int al3 = __float_as_uint(Al[base + 8 * SLD + 4]);
#pragma unroll
                for (int fn = 0; fn < 4; fn++) {
                    MMA_TF32(acc[fm][fn][0], acc[fm][fn][1], acc[fm][fn][2], acc[fm][fn][3],
                             ah0, ah1, ah2, ah3, bh0[fn], bh1[fn]);
                    MMA_TF32(acc[fm][fn][0], acc[fm][fn][1], acc[fm][fn][2], acc[fm][fn][3],
                             ah0, ah1, ah2, ah3, bl0[fn], bl1[fn]);
                    MMA_TF32(acc[fm][fn][0], acc[fm][fn][1], acc[fm][fn][2], acc[fm][fn][3],
                             al0, al1, al2, al3, bh0[fn], bh1[fn]);
                }
            }
        }
        __syncthreads();
    }

#pragma unroll
    for (int fm = 0; fm < 4; fm++) {
#pragma unroll
        for (int fn = 0; fn < 4; fn++) {
            int c0 = wn + fn * 8 + lc * 2;
            float bx = bias[c0], by = bias[c0 + 1];
            int r0 = bm + wm + fm * 16 + lr;
            int r1 = r0 + 8;
            if (r0 < M) {
                float2 o;
                o.x = fmaxf(acc[fm][fn][0] + bx, 0.f);
                o.y = fmaxf(acc[fm][fn][1] + by, 0.f);
                *reinterpret_cast<float2*>(&g_h1[(size_t)r0 * Nd + c0]) = o;
            }
            if (r1 < M) {
                float2 o;
                o.x = fmaxf(acc[fm][fn][2] + bx, 0.f);
                o.y = fmaxf(acc[fm][fn][3] + by, 0.f);
                *reinterpret_cast<float2*>(&g_h1[(size_t)r1 * Nd + c0]) = o;
            }
        }
    }
}

// ---------------------------------------------------------------------------
// Fused layer2+layer3: same conflict-free tf32 mainloop, then h2 -> smem
// (aliasing the stage arrays), pps[0] = relu(h2 @ W3^T + b3).
// ---------------------------------------------------------------------------
#define H2_LD (HID + 4)
__global__ __launch_bounds__(256, 2)
void gemm2_lin3_fused(const float* __restrict__ b2,
                      const float* __restrict__ W2,
                      const float* __restrict__ W3,
                      const float* __restrict__ b3)
{
    constexpr int BM = 128, BK = 32, Kd = HID;
    const int M = N_NODES;
    const float* __restrict__ A = g_h1;

    extern __shared__ float sm[];
    float* Ah = sm;
    float* Al = sm + SARR;
    float* Wh = sm + 2 * SARR;
    float* Wl = sm + 3 * SARR;
    float (*h2s)[H2_LD] = (float(*)[H2_LD])sm;                  // aliases stage arrays
    float (*W3s)[CH]    = (float(*)[CH])(sm + 4 * SARR);
    float* b3s          = sm + 4 * SARR + HID * CH;

    const int tid  = threadIdx.x;
    const int lane = tid & 31;
    const int wid  = tid >> 5;
    const int wm   = (wid >> 2) * 64;
    const int wn   = (wid & 3) * 32;
    const int lr   = lane >> 2;
    const int lc   = lane & 3;
    const int bm   = blockIdx.x * BM;

    for (int i = tid; i < CH * HID; i += 256) {
        int c = i / HID, k = i % HID;
        W3s[k][c] = W3[(size_t)c * HID + k];
    }
    if (tid < CH) b3s[tid] = b3[tid];

    float acc[4][4][4];
#pragma unroll
    for (int i = 0; i < 4; i++)
#pragma unroll
        for (int j = 0; j < 4; j++)
#pragma unroll
            for (int r = 0; r < 4; r++) acc[i][j][r] = 0.f;

    const int grow = tid >> 3;
    const int gcol = (tid & 7) * 4;

    for (int s = 0; s < Kd / BK; s++) {
        const int k0 = s * BK;
#pragma unroll
        for (int r = 0; r < 4; r++) {
            int row = grow + r * 32;
            int gm  = bm + row;
            float4 v = make_float4(0.f, 0.f, 0.f, 0.f);
            if (gm < M)
                v = *reinterpret_cast<const float4*>(&A[(size_t)gm * Kd + k0 + gcol]);
            int base = row * SLD + gcol;
            split_store(Ah, Al, base + 0, v.x);
            split_store(Ah, Al, base + 1, v.y);
            split_store(Ah, Al, base + 2, v.z);
            split_store(Ah, Al, base + 3, v.w);
            float4 wv = *reinterpret_cast<const float4*>(&W2[(size_t)row * Kd + k0 + gcol]);
            split_store(Wh, Wl, base + 0, wv.x);
            split_store(Wh, Wl, base + 1, wv.y);
            split_store(Wh, Wl, base + 2, wv.z);
            split_store(Wh, Wl, base + 3, wv.w);
        }
        __syncthreads();

#pragma unroll
        for (int k = 0; k < BK; k += 8) {
            unsigned int bh0[4], bh1[4], bl0[4], bl1[4];
#pragma unroll
            for (int fn = 0; fn < 4; fn++) {
                int base = (wn + fn * 8 + lr) * SLD + k + lc;
                bh0[fn] = __float_as_uint(Wh[base]);
                bh1[fn] = __float_as_uint(Wh[base + 4]);
                bl0[fn] = __float_as_uint(Wl[base]);
                bl1[fn] = __float_as_uint(Wl[base + 4]);
            }
#pragma unroll
            for (int fm = 0; fm < 4; fm++) {
                int base = (wm + fm * 16 + lr) * SLD + k + lc;
                unsigned int ah0 = __float_as_uint(Ah[base]);
                unsigned int ah1 = __float_as_uint(Ah[base + 8 * SLD]);
                unsigned int ah2 = __float_as_uint(Ah[base + 4]);
                unsigned int ah3 = __float_as_uint(Ah[base + 8 * SLD + 4]);
                unsigned int al0 = __float_as_uint(Al[base]);
                unsigned int al1 = __float_as_uint(Al[base + 8 * SLD]);
                unsigned int al2 = __float_as_uint(Al[base + 4]);
                unsigned int al3 = __float_as_uint(Al[base + 8 * SLD + 4]);
#pragma unroll
                for (int fn = 0; fn < 4; fn++) {
                    MMA_TF32(acc[fm][fn][0], acc[fm][fn][1], acc[fm][fn][2], acc[fm][fn][3],
                             ah0, ah1, ah2, ah3, bh0[fn], bh1[fn]);
                    MMA_TF32(acc[fm][fn][0], acc[fm][fn][1], acc[fm][fn][2], acc[fm][fn][3],
                             ah0, ah1, ah2, ah3, bl0[fn], bl1[fn]);
                    MMA_TF32(acc[fm][fn][0], acc[fm][fn][1], acc[fm][fn][2], acc[fm][fn][3],
                             al0, al1, al2, al3, bh0[fn], bh1[fn]);
                }
            }
        }
        __syncthreads();   // after last stage, Ah/Al/Wh/Wl dead -> h2s aliases
    }

    // bias2 + relu -> h2 tile in smem
#pragma unroll
    for (int fm = 0; fm < 4; fm++) {
#pragma unroll
        for (int fn = 0; fn < 4; fn++) {
            int c0 = wn + fn * 8 + lc * 2;
            float bx = b2[c0], by = b2[c0 + 1];
            int r0 = wm + fm * 16 + lr;
            int r1 = r0 + 8;
            h2s[r0][c0]     = fmaxf(acc[fm][fn][0] + bx, 0.f);
            h2s[r0][c0 + 1] = fmaxf(acc[fm][fn][1] + by, 0.f);
            h2s[r1][c0]     = fmaxf(acc[fm][fn][2] + bx, 0.f);
            h2s[r1][c0 + 1] = fmaxf(acc[fm][fn][3] + by, 0.f);
        }
    }
    __syncthreads();

    // pps[0] = relu(h2 @ W3^T + b3)
    const int c2 = tid & 15;
    const int g2 = tid >> 4;
    const float b3v = b3s[c2];
#pragma unroll
    for (int i = 0; i < 8; i++) {
        int r = g2 * 8 + i;
        float acc3 = 0.f;
#pragma unroll
        for (int k = 0; k < HID; k += 4) {
            float4 hv = *reinterpret_cast<const float4*>(&h2s[r][k]);
            acc3 += hv.x * W3s[k + 0][c2];
            acc3 += hv.y * W3s[k + 1][c2];
            acc3 += hv.z * W3s[k + 2][c2];
            acc3 += hv.w * W3s[k + 3][c2];
        }
        int gm = bm + r;
        if (gm < M)
            g_pps[(size_t)gm * CH + c2] = fmaxf(acc3 + b3v, 0.f);
    }
}

// ---------------------------------------------------------------------------
// Pull-mode hop: warp per dst node, 4 lanes/edge x 8 edges/iter,
// 2-way unrolled, shfl-reduce, coalesced float4 store. No atomics.
// ---------------------------------------------------------------------------
__global__ void hop_pull(int k)
{
    const float* __restrict__ hin = g_pps + (size_t)k * N_NODES * CH;
    float* __restrict__ hout = g_pps + (size_t)(k + 1) * N_NODES * CH;

    int node = (blockIdx.x * blockDim.x + threadIdx.x) >> 5;
    if (node >= N_NODES) return;
    const int lane = threadIdx.x & 31;
    const int w = lane >> 2;
    const int q = lane & 3;
    const int qoff = q * 4;

    const int rs = __ldg(&g_row[node]);
    const int re = __ldg(&g_row[node + 1]);

    float4 acc0 = make_float4(0.f, 0.f, 0.f, 0.f);
    float4 acc1 = make_float4(0.f, 0.f, 0.f, 0.f);

    int e = rs + w;
    for (; e + 8 < re; e += 16) {
        int2 ed0 = __ldg(&g_csr[e]);
        int2 ed1 = __ldg(&g_csr[e + 8]);
        float4 v0 = *reinterpret_cast<const float4*>(hin + ed0.x * CH + qoff);
        float4 v1 = *reinterpret_cast<const float4*>(hin + ed1.x * CH + qoff);
        float w0 = __int_as_float(ed0.y);
        float w1 = __int_as_float(ed1.y);
        acc0.x += w0 * v0.x; acc0.y += w0 * v0.y;
        acc0.z += w0 * v0.z; acc0.w += w0 * v0.w;
        acc1.x += w1 * v1.x; acc1.y += w1 * v1.y;
        acc1.z += w1 * v1.z; acc1.w += w1 * v1.w;
    }
    if (e < re) {
        int2 ed0 = __ldg(&g_csr[e]);
        float4 v0 = *reinterpret_cast<const float4*>(hin + ed0.x * CH + qoff);
        float w0 = __int_as_float(ed0.y);
        acc0.x += w0 * v0.x; acc0.y += w0 * v0.y;
        acc0.z += w0 * v0.z; acc0.w += w0 * v0.w;
    }

    float4 acc = make_float4(acc0.x + acc1.x, acc0.y + acc1.y,
                             acc0.z + acc1.z, acc0.w + acc1.w);

#pragma unroll
    for (int off = 4; off <= 16; off <<= 1) {
        acc.x += __shfl_xor_sync(0xffffffff, acc.x, off);
        acc.y += __shfl_xor_sync(0xffffffff, acc.y, off);
        acc.z += __shfl_xor_sync(0xffffffff, acc.z, off);
        acc.w += __shfl_xor_sync(0xffffffff, acc.w, off);
    }

    if (w == 0)
        *reinterpret_cast<float4*>(hout + node * CH + qoff) = acc;
}

// ---------------------------------------------------------------------------
// Combine
// ---------------------------------------------------------------------------
__global__ void combine_kernel(const float* __restrict__ proj_w,
                               const float* __restrict__ proj_b,
                               float* __restrict__ out)
{
    int n = blockIdx.x * blockDim.x + threadIdx.x;
    if (n >= N_NODES) return;

    float w[CH];
#pragma unroll
    for (int c = 0; c < CH; c++) w[c] = proj_w[c];
    const float pb = proj_b[0];

    float acc[CH];
#pragma unroll
    for (int c = 0; c < CH; c++) acc[c] = 0.f;

#pragma unroll
    for (int k = 0; k <= K_HOPS; k++) {
        const float4* p = reinterpret_cast<const float4*>(
            g_pps + (size_t)k * N_NODES * CH + (size_t)n * CH);
        float4 v0 = p[0], v1 = p[1], v2 = p[2], v3 = p[3];
        float pv[CH] = {v0.x, v0.y, v0.z, v0.w, v1.x, v1.y, v1.z, v1.w,
                        v2.x, v2.y, v2.z, v2.w, v3.x, v3.y, v3.z, v3.w};
        float sdot = pb;
#pragma unroll
        for (int c = 0; c < CH; c++) sdot += pv[c] * w[c];
        float s = 1.0f / (1.0f + expf(-sdot));
#pragma unroll
        for (int c = 0; c < CH; c++) acc[c] += s * pv[c];
    }

    float4* o = reinterpret_cast<float4*>(out + (size_t)n * CH);
    o[0] = make_float4(acc[0],  acc[1],  acc[2],  acc[3]);
    o[1] = make_float4(acc[4],  acc[5],  acc[6],  acc[7]);
    o[2] = make_float4(acc[8],  acc[9],  acc[10], acc[11]);
    o[3] = make_float4(acc[12], acc[13], acc[14], acc[15]);
}

// ---------------------------------------------------------------------------
extern "C" void kernel_launch(void* const* d_in, const int* in_sizes, int n_in,
                              void* d_out, int out_size)
{
    const float* x    = (const float*)d_in[0];
    const void*  ei   = d_in[1];
    const float* attr = (const float*)d_in[2];
    const float* w1   = (const float*)d_in[3];
    const float* b1   = (const float*)d_in[4];
    const float* w2   = (const float*)d_in[5];
    const float* b2   = (const float*)d_in[6];
    const float* w3   = (const float*)d_in[7];
    const float* b3   = (const float*)d_in[8];
    const float* pw   = (const float*)d_in[9];
    const float* pbv  = (const float*)d_in[10];
    float* out = (float*)d_out;

    const int G1_SMEM = STAGE_BYTES;                              // 73728
    const int G2_SMEM = STAGE_BYTES + HID * CH * 4 + 64;          // ~82 KB
    cudaFuncSetAttribute(gemm1_tf32,
                         cudaFuncAttributeMaxDynamicSharedMemorySize, G1_SMEM);
    cudaFuncSetAttribute(gemm2_lin3_fused,
                         cudaFuncAttributeMaxDynamicSharedMemorySize, G2_SMEM);

    const int EB = (NE + 255) / 256;
    const int grid1 = (N_NODES + 127) / 128;

    // Launch order keeps gemm1_tf32 at slot 4 — the slot ncu captures.
    detect_idx_dtype<<<1, 32>>>((const unsigned int*)ei);           // 1
    zero_cnt<<<NBLK, 256>>>();                                      // 2
    hist_kernel<<<EB, 256>>>(ei);                                   // 3
    gemm1_tf32<<<grid1, 256, G1_SMEM>>>(x, w1, b1);                 // 4  <- profiled
    scan_blocks<<<NBLK, 256>>>();                                   // 5
    scan_tops<<<1, 512>>>();                                        // 6
    finalize_row<<<NBLK, 256>>>();                                  // 7
    scatter_csr<<<EB, 256>>>(ei, attr);                             // 8
    gemm2_lin3_fused<<<grid1, 256, G2_SMEM>>>(b2, w2, w3, b3);      // 9

    // K pull-mode hops (warp per node)
    {
        int blocks = (N_NODES * 32 + 255) / 256;
        for (int k = 0; k < K_HOPS; k++)
            hop_pull<<<blocks, 256>>>(k);
    }

    combine_kernel<<<(N_NODES + 255) / 256, 256>>>(pw, pbv, out);
}